// round 6
// baseline (speedup 1.0000x reference)
#include <cuda_runtime.h>
#include <math.h>

#define N_TOK 4096
#define D_DIM 2048
#define TK    1024
#define NSEL  128         // persistent selection CTAs (1 wave, <= 148 SMs)
#define EPSV  1e-6f

// ---------------- device global scratch (no allocations allowed) ----------------
__device__ float g_F[N_TOK][D_DIM];      // normalized features (32 MB)
__device__ float g_K[N_TOK][N_TOK];      // r_n * sim * r_m     (64 MB)
__device__ float g_C[N_TOK][TK];         // cis, token-major: g_C[m][t] = cis[t][m]
__device__ float g_r[N_TOK];
__device__ float g_di2s[N_TOK];
__device__ float g_mn, g_mx;
__device__ unsigned long long g_slot[TK + 2];
__device__ unsigned int g_done[TK + 2];

// ---------------- init: reset per-replay state ------------------------------------
__global__ void init_ker() {
    int t = blockIdx.x * blockDim.x + threadIdx.x;
    if (t < TK + 2) { g_slot[t] = 0ull; g_done[t] = 0u; }
}

// ---------------- min/max of relevance = -attn -------------------------------------
__global__ void minmax_ker(const float* __restrict__ attn) {
    __shared__ float smn[256], smx[256];
    int tid = threadIdx.x;
    float mn = INFINITY, mx = -INFINITY;
    for (int i = tid; i < N_TOK; i += 256) {
        float v = -attn[i];
        mn = fminf(mn, v); mx = fmaxf(mx, v);
    }
    smn[tid] = mn; smx[tid] = mx; __syncthreads();
    for (int s = 128; s > 0; s >>= 1) {
        if (tid < s) {
            smn[tid] = fminf(smn[tid], smn[tid + s]);
            smx[tid] = fmaxf(smx[tid], smx[tid + s]);
        }
        __syncthreads();
    }
    if (tid == 0) { g_mn = smn[0]; g_mx = smx[0]; }
}

__global__ void relev_ker(const float* __restrict__ attn) {
    int n = blockIdx.x * blockDim.x + threadIdx.x;
    if (n < N_TOK) {
        g_r[n] = ((-attn[n]) - g_mn + EPSV) / (g_mx - g_mn);
    }
}

// ---------------- row L2-normalize --------------------------------------------------
__global__ void norm_ker(const float* __restrict__ X) {
    int row = blockIdx.x;
    int tid = threadIdx.x;
    const float4* x4 = (const float4*)(X + (size_t)row * D_DIM);
    float4 v0 = x4[tid], v1 = x4[tid + 256];
    float ss = v0.x*v0.x + v0.y*v0.y + v0.z*v0.z + v0.w*v0.w
             + v1.x*v1.x + v1.y*v1.y + v1.z*v1.z + v1.w*v1.w;
    __shared__ float sred[256];
    sred[tid] = ss; __syncthreads();
    for (int s = 128; s > 0; s >>= 1) {
        if (tid < s) sred[tid] += sred[tid + s];
        __syncthreads();
    }
    float inv = 1.0f / sqrtf(sred[0]);
    v0.x *= inv; v0.y *= inv; v0.z *= inv; v0.w *= inv;
    v1.x *= inv; v1.y *= inv; v1.z *= inv; v1.w *= inv;
    float4* o4 = (float4*)(&g_F[row][0]);
    o4[tid] = v0; o4[tid + 256] = v1;
}

// ---------------- K = diag(r) * F F^T * diag(r), symmetric half --------------------
__global__ void __launch_bounds__(256) gemm_ker() {
    int bx = blockIdx.x, by = blockIdx.y;
    if (by > bx) return;                 // lower-triangular tiles only
    __shared__ float As[16][132];
    __shared__ float Bs[16][132];
    int tid = threadIdx.x;
    int tx = tid & 15, ty = tid >> 4;
    int lr = tid >> 2;                   // 0..63
    int lc = (tid & 3) * 4;              // 0,4,8,12
    const float* Ab = &g_F[bx * 128 + lr][lc];
    const float* Bb = &g_F[by * 128 + lr][lc];
    float acc[8][8];
    #pragma unroll
    for (int i = 0; i < 8; i++)
        #pragma unroll
        for (int j = 0; j < 8; j++) acc[i][j] = 0.f;

    for (int k0 = 0; k0 < D_DIM; k0 += 16) {
        float4 a0 = *(const float4*)(Ab + k0);
        float4 a1 = *(const float4*)(Ab + (size_t)64 * D_DIM + k0);
        float4 b0 = *(const float4*)(Bb + k0);
        float4 b1 = *(const float4*)(Bb + (size_t)64 * D_DIM + k0);
        As[lc + 0][lr] = a0.x; As[lc + 1][lr] = a0.y; As[lc + 2][lr] = a0.z; As[lc + 3][lr] = a0.w;
        As[lc + 0][lr + 64] = a1.x; As[lc + 1][lr + 64] = a1.y; As[lc + 2][lr + 64] = a1.z; As[lc + 3][lr + 64] = a1.w;
        Bs[lc + 0][lr] = b0.x; Bs[lc + 1][lr] = b0.y; Bs[lc + 2][lr] = b0.z; Bs[lc + 3][lr] = b0.w;
        Bs[lc + 0][lr + 64] = b1.x; Bs[lc + 1][lr + 64] = b1.y; Bs[lc + 2][lr + 64] = b1.z; Bs[lc + 3][lr + 64] = b1.w;
        __syncthreads();
        #pragma unroll
        for (int kk = 0; kk < 16; kk++) {
            float4 ra0 = *(float4*)&As[kk][ty * 8];
            float4 ra1 = *(float4*)&As[kk][ty * 8 + 4];
            float4 rb0 = *(float4*)&Bs[kk][tx * 8];
            float4 rb1 = *(float4*)&Bs[kk][tx * 8 + 4];
            float a[8] = {ra0.x, ra0.y, ra0.z, ra0.w, ra1.x, ra1.y, ra1.z, ra1.w};
            float b[8] = {rb0.x, rb0.y, rb0.z, rb0.w, rb1.x, rb1.y, rb1.z, rb1.w};
            #pragma unroll
            for (int i = 0; i < 8; i++)
                #pragma unroll
                for (int j = 0; j < 8; j++) acc[i][j] += a[i] * b[j];
        }
        __syncthreads();
    }

    int r0 = bx * 128 + ty * 8;
    int c0 = by * 128 + tx * 8;
    float rr[8], rc[8];
    #pragma unroll
    for (int i = 0; i < 8; i++) rr[i] = g_r[r0 + i];
    #pragma unroll
    for (int j = 0; j < 8; j++) rc[j] = g_r[c0 + j];
    #pragma unroll
    for (int i = 0; i < 8; i++)
        #pragma unroll
        for (int j = 0; j < 8; j++) {
            float v = acc[i][j] * rr[i] * rc[j];
            g_K[r0 + i][c0 + j] = v;
            if (bx != by) g_K[c0 + j][r0 + i] = v;
        }
}

__global__ void diag_ker() {
    int n = blockIdx.x * 256 + threadIdx.x;
    if (n < N_TOK) g_di2s[n] = g_K[n][n];
}

// ---------------- key packing: order-preserving float + first-index tiebreak -------
__device__ __forceinline__ unsigned long long packkey(float f, int idx) {
    unsigned u = __float_as_uint(f);
    u = (u & 0x80000000u) ? ~u : (u | 0x80000000u);
    return ((unsigned long long)u << 32) | (unsigned)(0xFFFFFFFFu - (unsigned)idx);
}

// ---------------- initial argmax over di2s -----------------------------------------
__global__ void argmax0_ker() {
    int n = blockIdx.x * 1024 + threadIdx.x;
    int lane = threadIdx.x & 31;
    unsigned long long k = (n < N_TOK) ? packkey(g_di2s[n], n) : 0ull;
    #pragma unroll
    for (int o = 16; o; o >>= 1) {
        unsigned long long t = __shfl_xor_sync(0xffffffffu, k, o);
        if (t > k) k = t;
    }
    if (lane == 0 && k) atomicMax(&g_slot[0], k);
}

// ---------------- persistent greedy DPP selection ----------------------------------
// 128 CTAs x 256 threads; warp w of block b owns tokens (b*8+w)*4 .. +3
__global__ void __launch_bounds__(256, 1) select_ker(float* __restrict__ out, int topk) {
    __shared__ float cj_sh[TK];
    __shared__ unsigned long long warpmax[8];
    __shared__ unsigned long long s_key;

    int tid = threadIdx.x, lane = tid & 31, wid = tid >> 5;
    int m_base = ((int)blockIdx.x * 8 + wid) * 4;

    for (int i = 0; i < topk; i++) {
        // ---- wait for step-i inputs (slot[i] finalized by all CTAs) ----
        if (i > 0) {
            if (tid == 0) {
                while (*(volatile unsigned int*)&g_done[i] < (unsigned)NSEL) { }
                __threadfence();
            }
            __syncthreads();
        }
        if (tid == 0) s_key = *(volatile unsigned long long*)&g_slot[i];
        __syncthreads();

        unsigned long long key = s_key;
        int j = (int)(0xFFFFFFFFu - (unsigned)(key & 0xFFFFFFFFull));
        unsigned uv = (unsigned)(key >> 32);
        uv = (uv & 0x80000000u) ? (uv ^ 0x80000000u) : ~uv;
        float sd = sqrtf(__uint_as_float(uv));

        // OUTPUT AS FLOAT32 (harness output dtype)
        if (blockIdx.x == 0 && tid == 0) out[i] = (float)j;

        // ---- stage C[j][0..i) into shared (cross-CTA data: bypass L1) ----
        for (int t = tid; t < i; t += 256) cj_sh[t] = __ldcg(&g_C[j][t]);
        __syncthreads();

        int i4 = i >> 2;
        const float4* cj4 = (const float4*)cj_sh;
        unsigned long long best = 0ull;

        #pragma unroll
        for (int mi = 0; mi < 4; mi++) {
            int m = m_base + mi;
            const float* cm = &g_C[m][0];          // own tokens: own-SM coherent
            const float4* cm4 = (const float4*)cm;
            float cdot = 0.f;
            for (int t = lane; t < i4; t += 32) {
                float4 a = cj4[t], b = cm4[t];
                cdot += a.x * b.x + a.y * b.y + a.z * b.z + a.w * b.w;
            }
            for (int t = (i4 << 2) + lane; t < i; t += 32)
                cdot += cj_sh[t] * cm[t];
            #pragma unroll
            for (int o = 16; o; o >>= 1)
                cdot += __shfl_xor_sync(0xffffffffu, cdot, o);
            if (lane == 0) {
                float eis = (g_K[j][m] - cdot) / sd;
                g_C[m][i] = eis;
                float d = g_di2s[m] - eis * eis;
                if (m == j) d = -INFINITY;
                g_di2s[m] = d;
                unsigned long long k = packkey(d, m);
                if (k > best) best = k;
            }
        }

        if (i + 1 < topk) {
            if (lane == 0) warpmax[wid] = best;
            __syncthreads();
            if (wid == 0) {
                unsigned long long k = (lane < 8) ? warpmax[lane] : 0ull;
                #pragma unroll
                for (int o = 4; o; o >>= 1) {
                    unsigned long long t = __shfl_xor_sync(0xffffffffu, k, o);
                    if (t > k) k = t;
                }
                if (lane == 0 && k) atomicMax(&g_slot[i + 1], k);
            }
            // ---- publish: make writes + slot contribution visible, then signal ----
            __threadfence();
            __syncthreads();
            if (tid == 0) atomicAdd(&g_done[i + 1], 1u);
        }
    }
}

// ---------------- host entry --------------------------------------------------------
extern "C" void kernel_launch(void* const* d_in, const int* in_sizes, int n_in,
                              void* d_out, int out_size) {
    // Robust input selection by element count
    const float* feat = (const float*)d_in[0];
    const float* attn = (const float*)d_in[1];
    for (int k = 0; k < n_in; k++) {
        if (in_sizes[k] == N_TOK * D_DIM) feat = (const float*)d_in[k];
        else if (in_sizes[k] == N_TOK)    attn = (const float*)d_in[k];
    }
    int topk = out_size;
    if (topk > TK) topk = TK;

    init_ker<<<2, 1024>>>();
    minmax_ker<<<1, 256>>>(attn);
    relev_ker<<<16, 256>>>(attn);
    norm_ker<<<N_TOK, 256>>>(feat);
    gemm_ker<<<dim3(32, 32), 256>>>();
    diag_ker<<<16, 256>>>();
    argmax0_ker<<<4, 1024>>>();
    select_ker<<<NSEL, 256>>>((float*)d_out, topk);
}

// round 7
// speedup vs baseline: 1.3988x; 1.3988x over previous
#include <cuda_runtime.h>
#include <math.h>

#define N_TOK 4096
#define D_DIM 2048
#define TK    1024
#define NSEL  128         // persistent selection CTAs (1 wave), 32 tokens each
#define TPB   32          // tokens per CTA
#define EPSV  1e-6f

// ---------------- device global scratch (no allocations allowed) ----------------
__device__ float g_F[N_TOK][D_DIM];      // normalized features (32 MB)
__device__ float g_K[N_TOK][N_TOK];      // r_n * sim * r_m     (64 MB)
__device__ float g_C[N_TOK][TK];         // cis, token-major: g_C[m][t] = cis[t][m]
__device__ float g_r[N_TOK];
__device__ float g_di2s[N_TOK];
__device__ float g_mn, g_mx;
__device__ unsigned long long g_slot[TK + 2];
__device__ unsigned int g_done[TK + 2];

// ---------------- init: reset per-replay state ------------------------------------
__global__ void init_ker() {
    int t = blockIdx.x * blockDim.x + threadIdx.x;
    if (t < TK + 2) { g_slot[t] = 0ull; g_done[t] = 0u; }
}

// ---------------- min/max of relevance = -attn -------------------------------------
__global__ void minmax_ker(const float* __restrict__ attn) {
    __shared__ float smn[256], smx[256];
    int tid = threadIdx.x;
    float mn = INFINITY, mx = -INFINITY;
    for (int i = tid; i < N_TOK; i += 256) {
        float v = -attn[i];
        mn = fminf(mn, v); mx = fmaxf(mx, v);
    }
    smn[tid] = mn; smx[tid] = mx; __syncthreads();
    for (int s = 128; s > 0; s >>= 1) {
        if (tid < s) {
            smn[tid] = fminf(smn[tid], smn[tid + s]);
            smx[tid] = fmaxf(smx[tid], smx[tid + s]);
        }
        __syncthreads();
    }
    if (tid == 0) { g_mn = smn[0]; g_mx = smx[0]; }
}

__global__ void relev_ker(const float* __restrict__ attn) {
    int n = blockIdx.x * blockDim.x + threadIdx.x;
    if (n < N_TOK) {
        g_r[n] = ((-attn[n]) - g_mn + EPSV) / (g_mx - g_mn);
    }
}

// ---------------- row L2-normalize --------------------------------------------------
__global__ void norm_ker(const float* __restrict__ X) {
    int row = blockIdx.x;
    int tid = threadIdx.x;
    const float4* x4 = (const float4*)(X + (size_t)row * D_DIM);
    float4 v0 = x4[tid], v1 = x4[tid + 256];
    float ss = v0.x*v0.x + v0.y*v0.y + v0.z*v0.z + v0.w*v0.w
             + v1.x*v1.x + v1.y*v1.y + v1.z*v1.z + v1.w*v1.w;
    __shared__ float sred[256];
    sred[tid] = ss; __syncthreads();
    for (int s = 128; s > 0; s >>= 1) {
        if (tid < s) sred[tid] += sred[tid + s];
        __syncthreads();
    }
    float inv = 1.0f / sqrtf(sred[0]);
    v0.x *= inv; v0.y *= inv; v0.z *= inv; v0.w *= inv;
    v1.x *= inv; v1.y *= inv; v1.z *= inv; v1.w *= inv;
    float4* o4 = (float4*)(&g_F[row][0]);
    o4[tid] = v0; o4[tid + 256] = v1;
}

// ---------------- K = diag(r) * F F^T * diag(r), symmetric half --------------------
__global__ void __launch_bounds__(256) gemm_ker() {
    int bx = blockIdx.x, by = blockIdx.y;
    if (by > bx) return;                 // lower-triangular tiles only
    __shared__ float As[16][132];
    __shared__ float Bs[16][132];
    int tid = threadIdx.x;
    int tx = tid & 15, ty = tid >> 4;
    int lr = tid >> 2;                   // 0..63
    int lc = (tid & 3) * 4;              // 0,4,8,12
    const float* Ab = &g_F[bx * 128 + lr][lc];
    const float* Bb = &g_F[by * 128 + lr][lc];
    float acc[8][8];
    #pragma unroll
    for (int i = 0; i < 8; i++)
        #pragma unroll
        for (int j = 0; j < 8; j++) acc[i][j] = 0.f;

    for (int k0 = 0; k0 < D_DIM; k0 += 16) {
        float4 a0 = *(const float4*)(Ab + k0);
        float4 a1 = *(const float4*)(Ab + (size_t)64 * D_DIM + k0);
        float4 b0 = *(const float4*)(Bb + k0);
        float4 b1 = *(const float4*)(Bb + (size_t)64 * D_DIM + k0);
        As[lc + 0][lr] = a0.x; As[lc + 1][lr] = a0.y; As[lc + 2][lr] = a0.z; As[lc + 3][lr] = a0.w;
        As[lc + 0][lr + 64] = a1.x; As[lc + 1][lr + 64] = a1.y; As[lc + 2][lr + 64] = a1.z; As[lc + 3][lr + 64] = a1.w;
        Bs[lc + 0][lr] = b0.x; Bs[lc + 1][lr] = b0.y; Bs[lc + 2][lr] = b0.z; Bs[lc + 3][lr] = b0.w;
        Bs[lc + 0][lr + 64] = b1.x; Bs[lc + 1][lr + 64] = b1.y; Bs[lc + 2][lr + 64] = b1.z; Bs[lc + 3][lr + 64] = b1.w;
        __syncthreads();
        #pragma unroll
        for (int kk = 0; kk < 16; kk++) {
            float4 ra0 = *(float4*)&As[kk][ty * 8];
            float4 ra1 = *(float4*)&As[kk][ty * 8 + 4];
            float4 rb0 = *(float4*)&Bs[kk][tx * 8];
            float4 rb1 = *(float4*)&Bs[kk][tx * 8 + 4];
            float a[8] = {ra0.x, ra0.y, ra0.z, ra0.w, ra1.x, ra1.y, ra1.z, ra1.w};
            float b[8] = {rb0.x, rb0.y, rb0.z, rb0.w, rb1.x, rb1.y, rb1.z, rb1.w};
            #pragma unroll
            for (int i = 0; i < 8; i++)
                #pragma unroll
                for (int j = 0; j < 8; j++) acc[i][j] += a[i] * b[j];
        }
        __syncthreads();
    }

    int r0 = bx * 128 + ty * 8;
    int c0 = by * 128 + tx * 8;
    float rr[8], rc[8];
    #pragma unroll
    for (int i = 0; i < 8; i++) rr[i] = g_r[r0 + i];
    #pragma unroll
    for (int j = 0; j < 8; j++) rc[j] = g_r[c0 + j];
    #pragma unroll
    for (int i = 0; i < 8; i++)
        #pragma unroll
        for (int j = 0; j < 8; j++) {
            float v = acc[i][j] * rr[i] * rc[j];
            g_K[r0 + i][c0 + j] = v;
            if (bx != by) g_K[c0 + j][r0 + i] = v;
        }
}

__global__ void diag_ker() {
    int n = blockIdx.x * 256 + threadIdx.x;
    if (n < N_TOK) g_di2s[n] = g_K[n][n];
}

// ---------------- key packing: order-preserving float + first-index tiebreak -------
__device__ __forceinline__ unsigned long long packkey(float f, int idx) {
    unsigned u = __float_as_uint(f);
    u = (u & 0x80000000u) ? ~u : (u | 0x80000000u);
    return ((unsigned long long)u << 32) | (unsigned)(0xFFFFFFFFu - (unsigned)idx);
}

// ---------------- initial argmax over di2s -----------------------------------------
__global__ void argmax0_ker() {
    int n = blockIdx.x * 1024 + threadIdx.x;
    int lane = threadIdx.x & 31;
    unsigned long long k = (n < N_TOK) ? packkey(g_di2s[n], n) : 0ull;
    #pragma unroll
    for (int o = 16; o; o >>= 1) {
        unsigned long long t = __shfl_xor_sync(0xffffffffu, k, o);
        if (t > k) k = t;
    }
    if (lane == 0 && k) atomicMax(&g_slot[0], k);
}

// ---------------- persistent greedy DPP selection (smem-resident C) ----------------
// 128 CTAs x 256 threads; CTA b owns tokens b*32 .. b*32+31; warp w handles 4 of them.
__global__ void __launch_bounds__(256, 1) select_ker(float* __restrict__ out, int topk) {
    extern __shared__ float sh[];
    float* C_sh  = sh;                    // [TPB][TK] = 128 KB, own C rows
    float* cj_sh = sh + TPB * TK;         // [TK]      = 4 KB
    __shared__ float di_sh[TPB];
    __shared__ unsigned long long warpmax[8];
    __shared__ unsigned long long s_key;

    int tid = threadIdx.x, lane = tid & 31, wid = tid >> 5;
    int m0 = (int)blockIdx.x * TPB;

    if (tid < TPB) di_sh[tid] = g_di2s[m0 + tid];
    __syncthreads();

    for (int i = 0; i < topk; i++) {
        // ---- wait for step-i inputs (slot[i] finalized by all CTAs) ----
        if (i > 0) {
            if (tid == 0) {
                while (*(volatile unsigned int*)&g_done[i] < (unsigned)NSEL) { }
                __threadfence();
            }
            __syncthreads();
        }
        if (tid == 0) s_key = *(volatile unsigned long long*)&g_slot[i];
        __syncthreads();

        unsigned long long key = s_key;
        int j = (int)(0xFFFFFFFFu - (unsigned)(key & 0xFFFFFFFFull));
        unsigned uv = (unsigned)(key >> 32);
        uv = (uv & 0x80000000u) ? (uv ^ 0x80000000u) : ~uv;
        float sd = sqrtf(__uint_as_float(uv));

        if (blockIdx.x == 0 && tid == 0) out[i] = (float)j;   // float32 output

        // ---- stage C[j][0..i) into shared (cross-CTA data: bypass L1) ----
        for (int t = tid; t < i; t += 256) cj_sh[t] = __ldcg(&g_C[j][t]);
        __syncthreads();

        int i4 = i >> 2;
        const float4* cj4 = (const float4*)cj_sh;
        unsigned long long best = 0ull;

        #pragma unroll
        for (int mi = 0; mi < 4; mi++) {
            int ml = wid * 4 + mi;                 // local token 0..31
            int m  = m0 + ml;
            const float*  cm  = C_sh + ml * TK;    // smem-resident own row
            const float4* cm4 = (const float4*)cm;
            float cdot = 0.f;
            for (int t = lane; t < i4; t += 32) {
                float4 a = cj4[t], b = cm4[t];
                cdot += a.x * b.x + a.y * b.y + a.z * b.z + a.w * b.w;
            }
            for (int t = (i4 << 2) + lane; t < i; t += 32)
                cdot += cj_sh[t] * cm[t];
            #pragma unroll
            for (int o = 16; o; o >>= 1)
                cdot += __shfl_xor_sync(0xffffffffu, cdot, o);
            if (lane == 0) {
                float eis = (g_K[j][m] - cdot) / sd;
                C_sh[ml * TK + i] = eis;           // smem copy (own dots)
                g_C[m][i] = eis;                   // publish for other CTAs
                float d = di_sh[ml] - eis * eis;
                if (m == j) d = -INFINITY;
                di_sh[ml] = d;
                unsigned long long k = packkey(d, m);
                if (k > best) best = k;
            }
        }

        if (i + 1 < topk) {
            if (lane == 0) warpmax[wid] = best;
            __syncthreads();
            if (wid == 0) {
                unsigned long long k = (lane < 8) ? warpmax[lane] : 0ull;
                #pragma unroll
                for (int o = 4; o; o >>= 1) {
                    unsigned long long t = __shfl_xor_sync(0xffffffffu, k, o);
                    if (t > k) k = t;
                }
                if (lane == 0 && k) atomicMax(&g_slot[i + 1], k);
            }
            // ---- publish: make writes + slot contribution visible, then signal ----
            __threadfence();
            __syncthreads();
            if (tid == 0) atomicAdd(&g_done[i + 1], 1u);
        }
    }
}

// ---------------- host entry --------------------------------------------------------
extern "C" void kernel_launch(void* const* d_in, const int* in_sizes, int n_in,
                              void* d_out, int out_size) {
    // Robust input selection by element count
    const float* feat = (const float*)d_in[0];
    const float* attn = (const float*)d_in[1];
    for (int k = 0; k < n_in; k++) {
        if (in_sizes[k] == N_TOK * D_DIM) feat = (const float*)d_in[k];
        else if (in_sizes[k] == N_TOK)    attn = (const float*)d_in[k];
    }
    int topk = out_size;
    if (topk > TK) topk = TK;

    const int smem_sel = (TPB * TK + TK) * (int)sizeof(float);   // 132 KB
    cudaFuncSetAttribute(select_ker, cudaFuncAttributeMaxDynamicSharedMemorySize, smem_sel);

    init_ker<<<2, 1024>>>();
    minmax_ker<<<1, 256>>>(attn);
    relev_ker<<<16, 256>>>(attn);
    norm_ker<<<N_TOK, 256>>>(feat);
    gemm_ker<<<dim3(32, 32), 256>>>();
    diag_ker<<<16, 256>>>();
    argmax0_ker<<<4, 1024>>>();
    select_ker<<<NSEL, 256, smem_sel>>>((float*)d_out, topk);
}